// round 5
// baseline (speedup 1.0000x reference)
#include <cuda_runtime.h>

#define XH 130
#define XW 130
#define XC 64
#define NPIX (XH * XW)
#define NRED 16
#define NSPAN 196
#define NLAYERS 6
#define TILE 8
#define TS 14
#define NTB 17
#define NBLK (NTB * NTB)   // 289

// ---------------- scratch ----------------
__device__ float g_bufA[NPIX * XC];
__device__ float g_bufB[NPIX * XC];
__device__ float g_redT[NLAYERS][16 * 16 * 4];
__device__ unsigned g_cnt = 0;
__device__ unsigned g_gen = 0;

// ---------------- f32x2 helpers ----------------
__device__ __forceinline__ unsigned long long dup2(float k) {
    unsigned long long r;
    asm("mov.b64 %0, {%1, %1};" : "=l"(r) : "f"(k));
    return r;
}
__device__ __forceinline__ unsigned long long fma2(unsigned long long a,
                                                   unsigned long long b,
                                                   unsigned long long c) {
    unsigned long long d;
    asm("fma.rn.f32x2 %0, %1, %2, %3;" : "=l"(d) : "l"(a), "l"(b), "l"(c));
    return d;
}
__device__ __forceinline__ unsigned long long add2(unsigned long long a,
                                                   unsigned long long b) {
    unsigned long long d;
    asm("add.rn.f32x2 %0, %1, %2;" : "=l"(d) : "l"(a), "l"(b));
    return d;
}
__device__ __forceinline__ float2 unpack2(unsigned long long v) {
    float2 r;
    asm("mov.b64 {%0, %1}, %2;" : "=f"(r.x), "=f"(r.y) : "l"(v));
    return r;
}

// ---------------- grid-wide barrier (all CTAs co-resident) ----------------
__device__ __forceinline__ void gridsync() {
    __syncthreads();
    if (threadIdx.x == 0) {
        unsigned g = atomicAdd(&g_gen, 0u);
        __threadfence();
        if (atomicAdd(&g_cnt, 1u) == gridDim.x - 1) {
            atomicExch(&g_cnt, 0u);
            __threadfence();
            atomicAdd(&g_gen, 1u);
        } else {
            while (atomicAdd(&g_gen, 0u) == g) __nanosleep(64);
        }
        __threadfence();
    }
    __syncthreads();
}

// smem layout (floats)
#define SM_XS   0
#define SM_SKER (TS * TS * XC)                // 12544
#define SM_T2   (SM_SKER + 64 * 224)          // 26880
#define SM_BETA (SM_T2 + 1024)                // 27904
#define SM_TOT  (SM_BETA + 16)                // 27920 floats = 111,680 B

__global__ void __launch_bounds__(512, 2)
mega_kernel(const float* __restrict__ input,
            const float* __restrict__ conv_in_w, const float* __restrict__ conv_in_b,
            const float* __restrict__ red_w, const float* __restrict__ bn_gamma,
            const float* __restrict__ bn_beta,
            const float* __restrict__ span_w, const float* __restrict__ span_b,
            const float* __restrict__ conv_out_w, const float* __restrict__ conv_out_b,
            float* __restrict__ out) {
    extern __shared__ float sm[];
    int tid = threadIdx.x, lane = tid & 31, wp = tid >> 5;
    int bid = blockIdx.x;
    int by = bid / NTB, bx = bid % NTB;
    int y0 = by * TILE - 3, x0 = bx * TILE - 3;

    // ======== prep (CTAs 0..5 fold BN gamma into red_w, transposed) ========
    if (bid < NLAYERS) {
        for (int i = tid; i < 1024; i += 512) {
            int r = i >> 6, c = i & 63;
            g_redT[bid][((c >> 2) * 16 + r) * 4 + (c & 3)] =
                bn_gamma[bid * 16 + r] * red_w[(bid * 16 + r) * 64 + c];
        }
    }

    // ======== conv_in: 3->64, 3x3, pad 2, NCHW -> NHWC ========
    {
        float* ws = sm;
        float* bs = sm + 27 * 64;
        for (int i = tid; i < 27 * 64; i += 512) {
            int t = i >> 6, c = i & 63;
            ws[i] = conv_in_w[c * 27 + t];
        }
        if (tid < 64) bs[tid] = conv_in_b[tid];
        __syncthreads();
        int c = tid & 63, pg = tid >> 6;
        int gx = bx * TILE + pg;
#pragma unroll
        for (int i = 0; i < 8; i++) {
            int gy = by * TILE + i;
            if (gy < XH && gx < XW) {
                float acc = bs[c];
#pragma unroll
                for (int ic = 0; ic < 3; ic++)
#pragma unroll
                    for (int ky = 0; ky < 3; ky++) {
                        int yy = gy + ky - 2;
                        if (yy < 0 || yy >= 128) continue;
#pragma unroll
                        for (int kx = 0; kx < 3; kx++) {
                            int xx = gx + kx - 2;
                            if (xx < 0 || xx >= 128) continue;
                            acc = fmaf(ws[(ic * 9 + ky * 3 + kx) * 64 + c],
                                       input[(ic * 128 + yy) * 128 + xx], acc);
                        }
                    }
                g_bufA[(gy * XW + gx) * 64 + c] = acc;
            }
        }
    }
    gridsync();

    // ======== layer-invariant lane mappings for involution ========
    int jb   = (wp < 7) ? wp : ((wp < 14) ? wp - 7 : wp - 14);
    int sub  = (wp < 7) ? 0 : ((wp < 14) ? 1 : 2);
    int nsub = (jb < 2) ? 3 : 2;
    int j = jb * 32 + lane;
    bool jok = (j < NSPAN);
    int goff;
    {
        int g = j / 49, q = j % 49;
        goff = g * 56 + (q / 7) * 8 + (q % 7);
    }

    float* xs     = sm + SM_XS;
    float* sker   = sm + SM_SKER;
    float* redT_s = sker;
    float* t2_s   = sm + SM_T2;
    float* beta_s = sm + SM_BETA;

    // ======== 6 involution layers ========
    for (int l = 0; l < NLAYERS; l++) {
        const float* xin = (l & 1) ? g_bufB : g_bufA;
        float* xout      = (l & 1) ? g_bufA : g_bufB;
        const float* sw  = span_w + l * NSPAN * NRED;

        // span weights into registers
        unsigned long long wd[16], sbd = 0ull;
        {
            float wr[16];
#pragma unroll
            for (int q = 0; q < 4; q++) {
                float4 v = make_float4(0.f, 0.f, 0.f, 0.f);
                if (jok) v = *(const float4*)&sw[j * 16 + q * 4];
                wr[q * 4] = v.x; wr[q * 4 + 1] = v.y;
                wr[q * 4 + 2] = v.z; wr[q * 4 + 3] = v.w;
            }
#pragma unroll
            for (int r = 0; r < 16; r++) wd[r] = dup2(wr[r]);
            if (jok) sbd = dup2(span_b[l * NSPAN + j]);
        }

        // stage x tile (zero-padded halo), redT, beta
        for (int i = tid; i < TS * TS * 16; i += 512) {
            int q = i & 15, p = i >> 4;
            int yy = y0 + p / TS, xx = x0 + p % TS;
            float4 v = make_float4(0.f, 0.f, 0.f, 0.f);
            if (yy >= 0 && yy < XH && xx >= 0 && xx < XW)
                v = *(const float4*)&xin[(yy * XW + xx) * XC + q * 4];
            *(float4*)&xs[p * XC + q * 4] = v;
        }
        if (tid < 256) *(float4*)&redT_s[tid * 4] = *(const float4*)&g_redT[l][tid * 4];
        if (tid < 16) beta_s[tid] = bn_beta[l * 16 + tid];
        __syncthreads();

        // t phase
        {
            int p = tid >> 3;
            int rb = (tid & 7) * 2;
            int py = p >> 3, px = p & 7;
            const float* xp = &xs[((py + 3) * TS + (px + 3)) * XC];
            float a0 = 0.f, a1 = 0.f;
#pragma unroll
            for (int q = 0; q < 16; q++) {
                float4 xv = *(const float4*)&xp[q * 4];
                float4 w0 = *(const float4*)&redT_s[(q * 16 + rb) * 4];
                float4 w1 = *(const float4*)&redT_s[(q * 16 + rb + 1) * 4];
                a0 = fmaf(w0.x, xv.x, a0); a0 = fmaf(w0.y, xv.y, a0);
                a0 = fmaf(w0.z, xv.z, a0); a0 = fmaf(w0.w, xv.w, a0);
                a1 = fmaf(w1.x, xv.x, a1); a1 = fmaf(w1.y, xv.y, a1);
                a1 = fmaf(w1.z, xv.z, a1); a1 = fmaf(w1.w, xv.w, a1);
            }
            int base = (p >> 1) * 32 + (p & 1);
            t2_s[base + rb * 2]       = fmaxf(a0 + beta_s[rb], 0.f);
            t2_s[base + (rb + 1) * 2] = fmaxf(a1 + beta_s[rb + 1], 0.f);
        }
        __syncthreads();

        // ker phase
        for (int pair = sub; pair < 32; pair += nsub) {
            const ulonglong2* tp2 = (const ulonglong2*)&t2_s[pair * 32];
            unsigned long long accA = sbd, accB = 0ull;
#pragma unroll
            for (int i = 0; i < 8; i++) {
                ulonglong2 tv = tp2[i];
                accA = fma2(wd[2 * i],     tv.x, accA);
                accB = fma2(wd[2 * i + 1], tv.y, accB);
            }
            unsigned long long acc = add2(accA, accB);
            if (jok) {
                float2 k = unpack2(acc);
                sker[(pair * 2) * 224 + goff]     = k.x;
                sker[(pair * 2 + 1) * 224 + goff] = k.y;
            }
        }
        __syncthreads();

        // apply phase: warp = 2x2 pixel block
        {
            int px0 = (wp & 3) * 2, py0 = (wp >> 2) * 2;
            int g = lane >> 3;
            int c0 = lane * 2;
            unsigned long long acc[2][2] = {{0ull, 0ull}, {0ull, 0ull}};
#pragma unroll
            for (int dya = 0; dya < 8; dya++) {
                unsigned long long xr[8];
                const float* row = &xs[((py0 + dya) * TS + px0) * XC + c0];
#pragma unroll
                for (int dx = 0; dx < 8; dx++)
                    xr[dx] = *(const unsigned long long*)&row[dx * XC];
#pragma unroll
                for (int r = 0; r < 2; r++) {
                    int dy = dya - r;
                    if (dy < 0 || dy > 6) continue;
#pragma unroll
                    for (int c = 0; c < 2; c++) {
                        int pl = (py0 + r) * 8 + (px0 + c);
                        const float4* kp = (const float4*)&sker[(pl * 4 + g) * 56 + dy * 8];
                        float4 ka = kp[0], kb = kp[1];
                        acc[r][c] = fma2(dup2(ka.x), xr[c + 0], acc[r][c]);
                        acc[r][c] = fma2(dup2(ka.y), xr[c + 1], acc[r][c]);
                        acc[r][c] = fma2(dup2(ka.z), xr[c + 2], acc[r][c]);
                        acc[r][c] = fma2(dup2(ka.w), xr[c + 3], acc[r][c]);
                        acc[r][c] = fma2(dup2(kb.x), xr[c + 4], acc[r][c]);
                        acc[r][c] = fma2(dup2(kb.y), xr[c + 5], acc[r][c]);
                        acc[r][c] = fma2(dup2(kb.z), xr[c + 6], acc[r][c]);
                    }
                }
            }
#pragma unroll
            for (int r = 0; r < 2; r++)
#pragma unroll
                for (int c = 0; c < 2; c++) {
                    int gy = by * TILE + py0 + r;
                    int gx = bx * TILE + px0 + c;
                    if (gy < XH && gx < XW) {
                        float2 o = unpack2(acc[r][c]);
                        o.x = fmaxf(o.x, 0.f);
                        o.y = fmaxf(o.y, 0.f);
                        *(float2*)&xout[(gy * XW + gx) * XC + c0] = o;
                    }
                }
        }
        gridsync();
    }

    // ======== conv_out (64->12, 3x3, pad 0) + PixelShuffle(2), smem-staged ========
    if (bid < 256) {
        int oby = bid >> 4, obx = bid & 15;
        int oy0 = oby * 8, ox0 = obx * 8;
        float* xt = sm;                 // 10*10*64 = 6400
        float* wo = sm + 6400;          // 6912
        float* bo = wo + 6912;          // 12

        for (int i = tid; i < 10 * 10 * 16; i += 512) {
            int q = i & 15, pos = i >> 4;
            int yy = oy0 + pos / 10, xx = ox0 + pos % 10;
            *(float4*)&xt[pos * 64 + q * 4] =
                *(const float4*)&g_bufA[(yy * XW + xx) * 64 + q * 4];
        }
        for (int i = tid; i < 9 * 12 * 64; i += 512) {
            int c = i & 63;
            int rest = i >> 6;
            int oc = rest % 12, tap = rest / 12;
            wo[(tap * 12 + oc) * 64 + c] = conv_out_w[(oc * 64 + c) * 9 + tap];
        }
        if (tid < 12) bo[tid] = conv_out_b[tid];
        __syncthreads();

        int c0 = lane * 2;
#pragma unroll
        for (int k = 0; k < 4; k++) {
            int p = wp * 4 + k;
            int py = p >> 3, px = p & 7;
            float o[12];
#pragma unroll
            for (int oc = 0; oc < 12; oc++) o[oc] = 0.f;
#pragma unroll
            for (int ky = 0; ky < 3; ky++)
#pragma unroll
                for (int kx = 0; kx < 3; kx++) {
                    int tap = ky * 3 + kx;
                    float2 xv = *(const float2*)&xt[((py + ky) * 10 + (px + kx)) * 64 + c0];
#pragma unroll
                    for (int oc = 0; oc < 12; oc++) {
                        float2 wv = *(const float2*)&wo[(tap * 12 + oc) * 64 + c0];
                        o[oc] = fmaf(wv.x, xv.x, o[oc]);
                        o[oc] = fmaf(wv.y, xv.y, o[oc]);
                    }
                }
#pragma unroll
            for (int oc = 0; oc < 12; oc++) {
#pragma unroll
                for (int s = 16; s > 0; s >>= 1)
                    o[oc] += __shfl_xor_sync(0xffffffffu, o[oc], s);
            }
            if (lane == 0) {
                int gy = oy0 + py, gx = ox0 + px;
#pragma unroll
                for (int oc = 0; oc < 12; oc++) {
                    int co = oc >> 2, rem = oc & 3;
                    int dy = rem >> 1, dx = rem & 1;
                    out[(co * 256 + (2 * gy + dy)) * 256 + (2 * gx + dx)] = o[oc] + bo[oc];
                }
            }
        }
    }
}

// ---------------- launch ----------------
extern "C" void kernel_launch(void* const* d_in, const int* in_sizes, int n_in,
                              void* d_out, int out_size) {
    const float* input      = (const float*)d_in[0];
    const float* conv_in_w  = (const float*)d_in[1];
    const float* conv_in_b  = (const float*)d_in[2];
    const float* red_w      = (const float*)d_in[3];
    const float* bn_gamma   = (const float*)d_in[4];
    const float* bn_beta    = (const float*)d_in[5];
    const float* span_w     = (const float*)d_in[6];
    const float* span_b     = (const float*)d_in[7];
    const float* conv_out_w = (const float*)d_in[8];
    const float* conv_out_b = (const float*)d_in[9];
    float* out = (float*)d_out;

    const int SMEM = SM_TOT * 4;   // 111,680 B
    cudaFuncSetAttribute(mega_kernel, cudaFuncAttributeMaxDynamicSharedMemorySize, SMEM);

    mega_kernel<<<NBLK, 512, SMEM>>>(input, conv_in_w, conv_in_b,
                                     red_w, bn_gamma, bn_beta,
                                     span_w, span_b, conv_out_w, conv_out_b, out);
}

// round 6
// speedup vs baseline: 1.6664x; 1.6664x over previous
#include <cuda_runtime.h>

#define XH 130
#define XW 130
#define XC 64
#define NPIX (XH * XW)
#define NRED 16
#define NSPAN 196
#define NLAYERS 6
#define TILE 8
#define TS 14
#define NTB 17

// ---------------- scratch ----------------
__device__ float g_bufA[NPIX * XC];
__device__ float g_bufB[NPIX * XC];
__device__ float g_redT[NLAYERS][16 * 16 * 4];   // [q][r] float4 (gamma-folded)

// ---------------- f32x2 helpers ----------------
__device__ __forceinline__ unsigned long long dup2(float k) {
    unsigned long long r;
    asm("mov.b64 %0, {%1, %1};" : "=l"(r) : "f"(k));
    return r;
}
__device__ __forceinline__ unsigned long long fma2(unsigned long long a,
                                                   unsigned long long b,
                                                   unsigned long long c) {
    unsigned long long d;
    asm("fma.rn.f32x2 %0, %1, %2, %3;" : "=l"(d) : "l"(a), "l"(b), "l"(c));
    return d;
}
__device__ __forceinline__ float2 unpack2(unsigned long long v) {
    float2 r;
    asm("mov.b64 {%0, %1}, %2;" : "=f"(r.x), "=f"(r.y) : "l"(v));
    return r;
}

// ---------------- conv_in (3->64, 3x3, pad2, NCHW->NHWC) + prep merged ----------------
#define NCONV ((NPIX * XC + 255) / 256)   // 4225

__global__ void conv_in_kernel(const float* __restrict__ in,
                               const float* __restrict__ w,
                               const float* __restrict__ b,
                               const float* __restrict__ red_w,
                               const float* __restrict__ gamma,
                               float* __restrict__ out) {
    if (blockIdx.x >= NCONV) {
        // prep: gamma-fold red_w into [q][r] float4 layout
        int idx = (blockIdx.x - NCONV) * 256 + threadIdx.x;   // 0..6143
        int l = idx >> 10, rem = idx & 1023;
        int r = rem >> 6, c = rem & 63;
        g_redT[l][((c >> 2) * 16 + r) * 4 + (c & 3)] =
            gamma[l * 16 + r] * red_w[(l * 16 + r) * 64 + c];
        return;
    }
    __shared__ float ws[27 * 64];
    int tid = threadIdx.x;
    for (int i = tid; i < 27 * 64; i += 256) {
        int t = i >> 6, c = i & 63;
        ws[t * 64 + c] = w[c * 27 + t];
    }
    __syncthreads();
    int idx = blockIdx.x * 256 + tid;
    if (idx >= NPIX * XC) return;
    int c = idx & 63;
    int p = idx >> 6;
    int y = p / XW, x = p % XW;
    float acc = b[c];
#pragma unroll
    for (int i = 0; i < 3; i++)
#pragma unroll
        for (int ky = 0; ky < 3; ky++) {
            int yy = y + ky - 2;
            if (yy < 0 || yy >= 128) continue;
#pragma unroll
            for (int kx = 0; kx < 3; kx++) {
                int xx = x + kx - 2;
                if (xx < 0 || xx >= 128) continue;
                acc = fmaf(ws[(i * 9 + ky * 3 + kx) * 64 + c],
                           in[(i * 128 + yy) * 128 + xx], acc);
            }
        }
    out[p * 64 + c] = acc;
}

// ---------------- fused involution layer ----------------
#define SM_XS   0
#define SM_SKER (TS * TS * XC)                // 12544
#define SM_T2   (SM_SKER + 64 * 224)          // 26880
#define SM_BETA (SM_T2 + 1024)                // 27904
#define SM_TOT  (SM_BETA + 16)                // 27920 floats = 111,680 B

__global__ void __launch_bounds__(512, 2)
inv_kernel(const float* __restrict__ xin, float* __restrict__ xout,
           const float* __restrict__ redT4, const float* __restrict__ beta,
           const float* __restrict__ span_w, const float* __restrict__ span_b) {
    extern __shared__ float sm[];
    float* xs     = sm + SM_XS;
    float* sker   = sm + SM_SKER;
    float* redT_s = sker;            // alias: read in T phase, overwritten in K phase
    float* t2_s   = sm + SM_T2;
    float* beta_s = sm + SM_BETA;

    int tid = threadIdx.x, lane = tid & 31, w = tid >> 5;
    int by = blockIdx.x / NTB, bx = blockIdx.x % NTB;
    int y0 = by * TILE - 3, x0 = bx * TILE - 3;

    // ---- K-phase span weights into registers (warps 0-7), before any sync ----
    // lane handles j1 = (w&3)*32+lane (0..127) and j2 = j1+128 (valid < 196)
    float wr1[16], wr2[16], sb1 = 0.f, sb2 = 0.f;
    int goff1 = 0, goff2 = 0;
    bool j2ok = false;
    if (w < 8) {
        int j1 = (w & 3) * 32 + lane;
        int j2 = j1 + 128;
        j2ok = (j2 < NSPAN);
#pragma unroll
        for (int q = 0; q < 4; q++) {
            float4 v = *(const float4*)&span_w[j1 * 16 + q * 4];
            wr1[q * 4] = v.x; wr1[q * 4 + 1] = v.y; wr1[q * 4 + 2] = v.z; wr1[q * 4 + 3] = v.w;
            float4 u = make_float4(0.f, 0.f, 0.f, 0.f);
            if (j2ok) u = *(const float4*)&span_w[j2 * 16 + q * 4];
            wr2[q * 4] = u.x; wr2[q * 4 + 1] = u.y; wr2[q * 4 + 2] = u.z; wr2[q * 4 + 3] = u.w;
        }
        sb1 = span_b[j1];
        if (j2ok) sb2 = span_b[j2];
        { int g = j1 / 49, q = j1 % 49; goff1 = g * 56 + (q / 7) * 8 + (q % 7); }
        if (j2ok) { int g = j2 / 49, q = j2 % 49; goff2 = g * 56 + (q / 7) * 8 + (q % 7); }
    }

    // ---- stage x tile (zero-padded halo), redT, beta ----
    for (int i = tid; i < TS * TS * 16; i += 512) {
        int q = i & 15, p = i >> 4;
        int yy = y0 + p / TS, xx = x0 + p % TS;
        float4 v = make_float4(0.f, 0.f, 0.f, 0.f);
        if (yy >= 0 && yy < XH && xx >= 0 && xx < XW)
            v = *(const float4*)&xin[(yy * XW + xx) * XC + q * 4];
        *(float4*)&xs[p * XC + q * 4] = v;
    }
    if (tid < 256) *(float4*)&redT_s[tid * 4] = *(const float4*)&redT4[tid * 4];
    if (tid < 16) beta_s[tid] = beta[tid];
    __syncthreads();

    // ---- T phase (warps 0-3): lane = (rg 0..7, pg 0..15); 2 r x 4 px per lane ----
    if (w < 4) {
        int L = w * 32 + lane;            // 0..127
        int rg = L & 7, pg = L >> 3;
        int r0 = rg * 2;
        int px0 = pg * 4;
        int py = px0 >> 3, pxx = px0 & 7;
        const float* xp = &xs[((py + 3) * TS + (pxx + 3)) * XC];
        float acc[2][4];
#pragma unroll
        for (int a = 0; a < 2; a++)
#pragma unroll
            for (int i = 0; i < 4; i++) acc[a][i] = 0.f;
#pragma unroll
        for (int q = 0; q < 16; q++) {
            float4 w0 = *(const float4*)&redT_s[(q * 16 + r0) * 4];
            float4 w1 = *(const float4*)&redT_s[(q * 16 + r0 + 1) * 4];
#pragma unroll
            for (int i = 0; i < 4; i++) {
                float4 xv = *(const float4*)&xp[i * XC + q * 4];
                acc[0][i] = fmaf(w0.x, xv.x, acc[0][i]);
                acc[0][i] = fmaf(w0.y, xv.y, acc[0][i]);
                acc[0][i] = fmaf(w0.z, xv.z, acc[0][i]);
                acc[0][i] = fmaf(w0.w, xv.w, acc[0][i]);
                acc[1][i] = fmaf(w1.x, xv.x, acc[1][i]);
                acc[1][i] = fmaf(w1.y, xv.y, acc[1][i]);
                acc[1][i] = fmaf(w1.z, xv.z, acc[1][i]);
                acc[1][i] = fmaf(w1.w, xv.w, acc[1][i]);
            }
        }
#pragma unroll
        for (int a = 0; a < 2; a++) {
            int r = r0 + a;
            float bv = beta_s[r];
#pragma unroll
            for (int pj = 0; pj < 2; pj++) {
                int pair = pg * 2 + pj;
                float2 v = make_float2(fmaxf(acc[a][pj * 2] + bv, 0.f),
                                       fmaxf(acc[a][pj * 2 + 1] + bv, 0.f));
                *(float2*)&t2_s[pair * 32 + r * 2] = v;
            }
        }
    }
    __syncthreads();   // t done; redT_s dead -> sker writable

    // ---- K phase (warps 0-7): 2 j per lane, 16 pairs per warp ----
    if (w < 8) {
        int pbase = (w >> 2) * 16;
        unsigned long long sbd1 = dup2(sb1), sbd2 = dup2(sb2);
#pragma unroll 1
        for (int p = 0; p < 16; p++) {
            int pair = pbase + p;
            const ulonglong2* tp2 = (const ulonglong2*)&t2_s[pair * 32];
            unsigned long long a1 = sbd1, a2 = sbd2;
#pragma unroll
            for (int i = 0; i < 8; i++) {
                ulonglong2 tv = tp2[i];
                a1 = fma2(dup2(wr1[2 * i]),     tv.x, a1);
                a1 = fma2(dup2(wr1[2 * i + 1]), tv.y, a1);
                a2 = fma2(dup2(wr2[2 * i]),     tv.x, a2);
                a2 = fma2(dup2(wr2[2 * i + 1]), tv.y, a2);
            }
            float2 k1 = unpack2(a1);
            sker[(pair * 2) * 224 + goff1]     = k1.x;
            sker[(pair * 2 + 1) * 224 + goff1] = k1.y;
            if (j2ok) {
                float2 k2 = unpack2(a2);
                sker[(pair * 2) * 224 + goff2]     = k2.x;
                sker[(pair * 2 + 1) * 224 + goff2] = k2.y;
            }
        }
    }
    __syncthreads();

    // ---- A phase (warps 0-7): warp tile 2 wide x 4 tall (8 px), 2 ch/lane ----
    if (w < 8) {
        int px0 = (w & 3) * 2, py0 = (w >> 2) * 4;
        int g = lane >> 3;
        int c0 = lane * 2;
        float2 a[4][2];
#pragma unroll
        for (int r = 0; r < 4; r++)
#pragma unroll
            for (int c = 0; c < 2; c++) a[r][c] = make_float2(0.f, 0.f);

#pragma unroll
        for (int dya = 0; dya < 10; dya++) {
            float2 xr[8];
            const float* row = &xs[((py0 + dya) * TS + px0) * XC + c0];
#pragma unroll
            for (int dx = 0; dx < 8; dx++)
                xr[dx] = *(const float2*)&row[dx * XC];
#pragma unroll
            for (int r = 0; r < 4; r++) {
                int dy = dya - r;
                if (dy < 0 || dy > 6) continue;
#pragma unroll
                for (int c = 0; c < 2; c++) {
                    int pl = (py0 + r) * 8 + (px0 + c);
                    const float4* kp = (const float4*)&sker[(pl * 4 + g) * 56 + dy * 8];
                    float4 ka = kp[0], kb = kp[1];
                    a[r][c].x = fmaf(ka.x, xr[c + 0].x, a[r][c].x);
                    a[r][c].y = fmaf(ka.x, xr[c + 0].y, a[r][c].y);
                    a[r][c].x = fmaf(ka.y, xr[c + 1].x, a[r][c].x);
                    a[r][c].y = fmaf(ka.y, xr[c + 1].y, a[r][c].y);
                    a[r][c].x = fmaf(ka.z, xr[c + 2].x, a[r][c].x);
                    a[r][c].y = fmaf(ka.z, xr[c + 2].y, a[r][c].y);
                    a[r][c].x = fmaf(ka.w, xr[c + 3].x, a[r][c].x);
                    a[r][c].y = fmaf(ka.w, xr[c + 3].y, a[r][c].y);
                    a[r][c].x = fmaf(kb.x, xr[c + 4].x, a[r][c].x);
                    a[r][c].y = fmaf(kb.x, xr[c + 4].y, a[r][c].y);
                    a[r][c].x = fmaf(kb.y, xr[c + 5].x, a[r][c].x);
                    a[r][c].y = fmaf(kb.y, xr[c + 5].y, a[r][c].y);
                    a[r][c].x = fmaf(kb.z, xr[c + 6].x, a[r][c].x);
                    a[r][c].y = fmaf(kb.z, xr[c + 6].y, a[r][c].y);
                }
            }
        }
#pragma unroll
        for (int r = 0; r < 4; r++)
#pragma unroll
            for (int c = 0; c < 2; c++) {
                int gy = by * TILE + py0 + r;
                int gx = bx * TILE + px0 + c;
                if (gy < XH && gx < XW) {
                    float2 o = make_float2(fmaxf(a[r][c].x, 0.f), fmaxf(a[r][c].y, 0.f));
                    *(float2*)&xout[(gy * XW + gx) * XC + c0] = o;
                }
            }
    }
}

// ---------------- conv_out (64->12, 3x3) + PixelShuffle(2) ----------------
__global__ void conv_out_kernel(const float* __restrict__ x,
                                const float* __restrict__ w,
                                const float* __restrict__ b,
                                float* __restrict__ out) {
    __shared__ float wS[9 * 12 * 64];
    __shared__ float bS[12];
    int tid = threadIdx.x;
    for (int i = tid; i < 9 * 12 * 64; i += blockDim.x) {
        int c = i & 63;
        int rest = i >> 6;
        int oc = rest % 12, tap = rest / 12;
        wS[(tap * 12 + oc) * 64 + c] = w[(oc * 64 + c) * 9 + tap];
    }
    if (tid < 12) bS[tid] = b[tid];
    __syncthreads();

    int lane = tid & 31, warp = tid >> 5;
    int c0 = lane * 2;
    int nwarps = gridDim.x * (blockDim.x >> 5);
    for (int pix = blockIdx.x * (blockDim.x >> 5) + warp; pix < 128 * 128; pix += nwarps) {
        int y = pix >> 7, xc = pix & 127;
        float o[12];
#pragma unroll
        for (int oc = 0; oc < 12; oc++) o[oc] = 0.f;
#pragma unroll
        for (int ky = 0; ky < 3; ky++)
#pragma unroll
            for (int kx = 0; kx < 3; kx++) {
                int tap = ky * 3 + kx;
                float2 xv = *(const float2*)&x[((y + ky) * XW + (xc + kx)) * XC + c0];
#pragma unroll
                for (int oc = 0; oc < 12; oc++) {
                    float2 wv = *(const float2*)&wS[(tap * 12 + oc) * 64 + c0];
                    o[oc] = fmaf(wv.x, xv.x, o[oc]);
                    o[oc] = fmaf(wv.y, xv.y, o[oc]);
                }
            }
#pragma unroll
        for (int oc = 0; oc < 12; oc++) {
#pragma unroll
            for (int s = 16; s > 0; s >>= 1)
                o[oc] += __shfl_xor_sync(0xffffffffu, o[oc], s);
        }
        if (lane == 0) {
#pragma unroll
            for (int oc = 0; oc < 12; oc++) {
                int co = oc >> 2, rem = oc & 3;
                int dy = rem >> 1, dx = rem & 1;
                out[(co * 256 + (2 * y + dy)) * 256 + (2 * xc + dx)] = o[oc] + bS[oc];
            }
        }
    }
}

// ---------------- launch ----------------
extern "C" void kernel_launch(void* const* d_in, const int* in_sizes, int n_in,
                              void* d_out, int out_size) {
    const float* input      = (const float*)d_in[0];
    const float* conv_in_w  = (const float*)d_in[1];
    const float* conv_in_b  = (const float*)d_in[2];
    const float* red_w      = (const float*)d_in[3];
    const float* bn_gamma   = (const float*)d_in[4];
    const float* bn_beta    = (const float*)d_in[5];
    const float* span_w     = (const float*)d_in[6];
    const float* span_b     = (const float*)d_in[7];
    const float* conv_out_w = (const float*)d_in[8];
    const float* conv_out_b = (const float*)d_in[9];
    float* out = (float*)d_out;

    float *bufA, *bufB, *redT;
    cudaGetSymbolAddress((void**)&bufA, g_bufA);
    cudaGetSymbolAddress((void**)&bufB, g_bufB);
    cudaGetSymbolAddress((void**)&redT, g_redT);

    const int SMEM_INV = SM_TOT * 4;   // 111,680 B
    cudaFuncSetAttribute(inv_kernel, cudaFuncAttributeMaxDynamicSharedMemorySize, SMEM_INV);

    // conv_in + prep fused (extra 24 blocks do prep)
    conv_in_kernel<<<NCONV + 24, 256>>>(input, conv_in_w, conv_in_b,
                                        red_w, bn_gamma, bufA);

    for (int l = 0; l < NLAYERS; l++) {
        const float* src = (l & 1) ? bufB : bufA;
        float* dst       = (l & 1) ? bufA : bufB;
        inv_kernel<<<NTB * NTB, 512, SMEM_INV>>>(
            src, dst, redT + l * 1024, bn_beta + l * 16,
            span_w + l * NSPAN * NRED, span_b + l * NSPAN);
    }

    conv_out_kernel<<<512, 256>>>(bufA, conv_out_w, conv_out_b, out);
}